// round 16
// baseline (speedup 1.0000x reference)
#include <cuda_runtime.h>
#include <cuda_fp16.h>
#include <cstdint>

#define NN 50000
#define NE 1600000
#define HF 128
#define NH 4
#define NF 32
#define PAD 96
#define GEMM_TILE 128
#define GEMM_NB ((NN + GEMM_TILE - 1) / GEMM_TILE)  // 391

#define TSTRIDE 136
#define TILE_HB (128 * TSTRIDE * 2)
#define SM_TOT  (2 * TILE_HB)

// ---------------- device scratch ------------------------------------------
__device__ __half2 g_feath[(size_t)NN * 64];  // projected features fp16 [N,128]
__device__ float   g_el[NN * NH];
__device__ float   g_er[NN * NH];
__device__ int     g_cnt[NN];                 // degree/cursor; starts zeroed, re-zeroed by k_agg
__device__ int     g_bin[(size_t)NN * PAD];   // padded CSR bins
__device__ __align__(16) __half g_wt[128 * TSTRIDE];  // W transposed, fp16, smem layout

__device__ __forceinline__ float lrelu(float x) {
    return x > 0.f ? x : 0.2f * x;
}

__device__ __forceinline__ uint32_t smem_u32(const void* p) {
    uint32_t a;
    asm("{ .reg .u64 t; cvta.to.shared.u64 t, %1; cvt.u32.u64 %0, t; }" : "=r"(a) : "l"(p));
    return a;
}
__device__ __forceinline__ void ldsm_x4(uint32_t addr, uint32_t* r) {
    asm volatile("ldmatrix.sync.aligned.m8n8.x4.shared.b16 {%0,%1,%2,%3}, [%4];"
                 : "=r"(r[0]), "=r"(r[1]), "=r"(r[2]), "=r"(r[3]) : "r"(addr));
}
__device__ __forceinline__ void ldsm_x2(uint32_t addr, uint32_t* r) {
    asm volatile("ldmatrix.sync.aligned.m8n8.x2.shared.b16 {%0,%1}, [%2];"
                 : "=r"(r[0]), "=r"(r[1]) : "r"(addr));
}
__device__ __forceinline__ void mma16816(float* c, const uint32_t* a, const uint32_t* b) {
    asm volatile(
        "mma.sync.aligned.m16n8k16.row.col.f32.f16.f16.f32 "
        "{%0,%1,%2,%3}, {%4,%5,%6,%7}, {%8,%9}, {%0,%1,%2,%3};"
        : "+f"(c[0]), "+f"(c[1]), "+f"(c[2]), "+f"(c[3])
        : "r"(a[0]), "r"(a[1]), "r"(a[2]), "r"(a[3]), "r"(b[0]), "r"(b[1]));
}

// ---------------- prep: W fp32 -> fp16 transposed (once, on s2) -------------
__global__ void k_prep(const float* __restrict__ W) {
    int p = blockIdx.x * blockDim.x + threadIdx.x;
    if (p >= 128 * 64) return;
    int k  = p >> 6;
    int n2 = p & 63;
    float2 v = ((const float2*)W)[p];
    g_wt[(n2 * 2)     * TSTRIDE + k] = __float2half_rn(v.x);
    g_wt[(n2 * 2 + 1) * TSTRIDE + k] = __float2half_rn(v.y);
}

// ---------------- HMMA GEMM: feat = h @ W, fused el/er ----------------------
__global__ void __launch_bounds__(256) k_gemm(const float* __restrict__ h,
                                              const float* __restrict__ attn_l,
                                              const float* __restrict__ attn_r) {
    extern __shared__ char smem[];
    __half* As = (__half*)smem;
    __half* Bs = (__half*)(smem + TILE_HB);
    uint32_t sA = smem_u32(As);
    uint32_t sB = smem_u32(Bs);

    int tid  = threadIdx.x;
    int wid  = tid >> 5;
    int lane = tid & 31;
    int base = blockIdx.x * GEMM_TILE;

    for (int p = tid; p < 128 * 64; p += 256) {
        int r  = p >> 6;
        int c2 = p & 63;
        float2 v = make_float2(0.f, 0.f);
        int gr = base + r;
        if (gr < NN) v = *(const float2*)&h[(size_t)gr * 128 + c2 * 2];
        *(__half2*)&As[r * TSTRIDE + c2 * 2] = __floats2half2_rn(v.x, v.y);
    }
    for (int p = tid; p < TILE_HB / 16; p += 256)
        ((uint4*)Bs)[p] = ((const uint4*)g_wt)[p];
    __syncthreads();

    int mrow0 = (wid >> 1) * 32;
    int ncol0 = (wid & 1) * 64;

    float acc[2][8][4];
#pragma unroll
    for (int mi = 0; mi < 2; mi++)
#pragma unroll
        for (int ni = 0; ni < 8; ni++)
#pragma unroll
            for (int j = 0; j < 4; j++) acc[mi][ni][j] = 0.f;

#pragma unroll
    for (int ks = 0; ks < 8; ks++) {
        int k0 = ks * 16;
        uint32_t a[2][4];
#pragma unroll
        for (int mi = 0; mi < 2; mi++) {
            int row = mrow0 + mi * 16 + (lane & 15);
            int col = k0 + (lane >> 4) * 8;
            ldsm_x4(sA + (row * TSTRIDE + col) * 2, a[mi]);
        }
        uint32_t b[8][2];
#pragma unroll
        for (int ni = 0; ni < 8; ni++) {
            int n = ncol0 + ni * 8 + (lane & 7);
            int k = k0 + ((lane >> 3) & 1) * 8;
            ldsm_x2(sB + (n * TSTRIDE + k) * 2, b[ni]);
        }
#pragma unroll
        for (int mi = 0; mi < 2; mi++)
#pragma unroll
            for (int ni = 0; ni < 8; ni++)
                mma16816(acc[mi][ni], a[mi], b[ni]);
    }
    __syncthreads();

    __half* Cs = As;
#pragma unroll
    for (int mi = 0; mi < 2; mi++) {
        int r0 = mrow0 + mi * 16 + (lane >> 2);
#pragma unroll
        for (int ni = 0; ni < 8; ni++) {
            int cb = ncol0 + ni * 8 + (lane & 3) * 2;
            *(__half2*)&Cs[r0 * TSTRIDE + cb]       = __floats2half2_rn(acc[mi][ni][0], acc[mi][ni][1]);
            *(__half2*)&Cs[(r0 + 8) * TSTRIDE + cb] = __floats2half2_rn(acc[mi][ni][2], acc[mi][ni][3]);
        }
    }
    __syncthreads();

    float4 al = ((const float4*)attn_l)[lane];
    float4 ar = ((const float4*)attn_r)[lane];
    int hh = lane >> 3;

    for (int i = 0; i < 16; i++) {
        int r  = wid * 16 + i;
        int gr = base + r;
        uint2 u = *(uint2*)&Cs[r * TSTRIDE + lane * 4];
        float2 f0 = __half22float2(*(__half2*)&u.x);
        float2 f1 = __half22float2(*(__half2*)&u.y);
        if (gr < NN) ((uint2*)g_feath)[(size_t)gr * 32 + lane] = u;

        float pl = f0.x * al.x + f0.y * al.y + f1.x * al.z + f1.y * al.w;
        float pr = f0.x * ar.x + f0.y * ar.y + f1.x * ar.z + f1.y * ar.w;
#pragma unroll
        for (int d = 4; d >= 1; d >>= 1) {
            pl += __shfl_down_sync(0xffffffffu, pl, d, 8);
            pr += __shfl_down_sync(0xffffffffu, pr, d, 8);
        }
        if (gr < NN && (lane & 7) == 0) {
            g_el[gr * 4 + hh] = pl;
            g_er[gr * 4 + hh] = pr;
        }
    }
}

// ---------------- one-pass padded-bin CSR build (4 edges/thread) ------------
__global__ void k_build(const int* __restrict__ src, const int* __restrict__ dst) {
    int q = blockIdx.x * blockDim.x + threadIdx.x;
    if (q >= NE / 4) return;
    int4 s4 = ((const int4*)src)[q];
    int4 d4 = ((const int4*)dst)[q];
    int p0 = atomicAdd(&g_cnt[d4.x], 1);
    int p1 = atomicAdd(&g_cnt[d4.y], 1);
    int p2 = atomicAdd(&g_cnt[d4.z], 1);
    int p3 = atomicAdd(&g_cnt[d4.w], 1);
    if (p0 < PAD) g_bin[(size_t)d4.x * PAD + p0] = s4.x;
    if (p1 < PAD) g_bin[(size_t)d4.y * PAD + p1] = s4.y;
    if (p2 < PAD) g_bin[(size_t)d4.z * PAD + p2] = s4.z;
    if (p3 < PAD) g_bin[(size_t)d4.w * PAD + p3] = s4.w;
}

// ---------------- fused aggregate: packed-smem + f32x2 FFMA j-loop ----------
__device__ __forceinline__ unsigned long long f2u64(float2 v) {
    unsigned long long u;
    asm("mov.b64 %0, {%1, %2};" : "=l"(u) : "f"(v.x), "f"(v.y));
    return u;
}

__global__ void __launch_bounds__(256) k_agg(const float* __restrict__ bias,
                                             float* __restrict__ out) {
    __shared__ int2 s_pk[8][4][32];   // [warp][head][edge-lane] = {src, ex_bits}

    int w    = (blockIdx.x * blockDim.x + threadIdx.x) >> 5;
    int lane = threadIdx.x & 31;
    int wl   = threadIdx.x >> 5;
    if (w >= NN) return;

    int deg = g_cnt[w];
    if (deg > PAD) deg = PAD;
    int start = w * PAD;
    int end   = start + deg;
    float4 erd = ((const float4*)g_er)[w];
    int hh = lane >> 3;

    unsigned long long acc0 = 0ull, acc1 = 0ull;   // packed float2 accumulators
    float4 dsum = make_float4(0.f, 0.f, 0.f, 0.f);

    // stage-0 prefetch
    int    ps = 0;
    float4 pa = make_float4(0.f, 0.f, 0.f, 0.f);
    bool   pv = (start + lane) < end;
    if (pv) {
        ps = __ldg(&g_bin[(size_t)start + lane]);
        pa = ((const float4*)g_el)[ps];
    }

    const uint2* fbase = &((const uint2*)g_feath)[lane];

    for (int base = start; base < end; base += 32) {
        float4 ex4 = make_float4(0.f, 0.f, 0.f, 0.f);
        if (pv) {
            ex4.x = __expf(lrelu(pa.x + erd.x));
            ex4.y = __expf(lrelu(pa.y + erd.y));
            ex4.z = __expf(lrelu(pa.z + erd.z));
            ex4.w = __expf(lrelu(pa.w + erd.w));
            dsum.x += ex4.x; dsum.y += ex4.y; dsum.z += ex4.z; dsum.w += ex4.w;
        }
        s_pk[wl][0][lane] = make_int2(ps, __float_as_int(ex4.x));
        s_pk[wl][1][lane] = make_int2(ps, __float_as_int(ex4.y));
        s_pk[wl][2][lane] = make_int2(ps, __float_as_int(ex4.z));
        s_pk[wl][3][lane] = make_int2(ps, __float_as_int(ex4.w));
        __syncwarp();

        // next-stage prefetch overlaps the j-loop
        int ne = base + 32 + lane;
        pv = ne < end;
        ps = 0;
        if (pv) {
            ps = __ldg(&g_bin[(size_t)ne]);
            pa = ((const float4*)g_el)[ps];
        }

        int cnt = end - base;
        if (cnt >= 32) {
            // fast path: fixed trip count, fully unrolled, no per-iter bounds test
#pragma unroll
            for (int j = 0; j < 32; j++) {
                int2 pk = s_pk[wl][hh][j];
                uint2 u = __ldg(fbase + (size_t)pk.x * 32);
                float2 f0 = __half22float2(*(__half2*)&u.x);
                float2 f1 = __half22float2(*(__half2*)&u.y);
                unsigned long long ajp;
                asm("mov.b64 %0, {%1, %1};" : "=l"(ajp) : "r"(pk.y));
                asm("fma.rn.f32x2 %0, %1, %2, %0;" : "+l"(acc0) : "l"(f2u64(f0)), "l"(ajp));
                asm("fma.rn.f32x2 %0, %1, %2, %0;" : "+l"(acc1) : "l"(f2u64(f1)), "l"(ajp));
            }
        } else {
            for (int j = 0; j < cnt; j++) {
                int2 pk = s_pk[wl][hh][j];
                uint2 u = __ldg(fbase + (size_t)pk.x * 32);
                float2 f0 = __half22float2(*(__half2*)&u.x);
                float2 f1 = __half22float2(*(__half2*)&u.y);
                unsigned long long ajp;
                asm("mov.b64 %0, {%1, %1};" : "=l"(ajp) : "r"(pk.y));
                asm("fma.rn.f32x2 %0, %1, %2, %0;" : "+l"(acc0) : "l"(f2u64(f0)), "l"(ajp));
                asm("fma.rn.f32x2 %0, %1, %2, %0;" : "+l"(acc1) : "l"(f2u64(f1)), "l"(ajp));
            }
        }
        __syncwarp();
    }

    // unpack packed accumulators
    float4 acc;
    asm("mov.b64 {%0, %1}, %2;" : "=f"(acc.x), "=f"(acc.y) : "l"(acc0));
    asm("mov.b64 {%0, %1}, %2;" : "=f"(acc.z), "=f"(acc.w) : "l"(acc1));

#pragma unroll
    for (int d = 16; d >= 1; d >>= 1) {
        dsum.x += __shfl_xor_sync(0xffffffffu, dsum.x, d);
        dsum.y += __shfl_xor_sync(0xffffffffu, dsum.y, d);
        dsum.z += __shfl_xor_sync(0xffffffffu, dsum.z, d);
        dsum.w += __shfl_xor_sync(0xffffffffu, dsum.w, d);
    }
    float dh = (hh == 0) ? dsum.x : (hh == 1) ? dsum.y : (hh == 2) ? dsum.z : dsum.w;
    float r  = 1.f / fmaxf(dh, 1e-9f);

    float4 b4 = ((const float4*)bias)[lane];
    float4 v;
    v.x = fmaxf(acc.x * r + b4.x, 0.f);
    v.y = fmaxf(acc.y * r + b4.y, 0.f);
    v.z = fmaxf(acc.z * r + b4.z, 0.f);
    v.w = fmaxf(acc.w * r + b4.w, 0.f);

#pragma unroll
    for (int d = 8; d <= 16; d <<= 1) {
        v.x += __shfl_xor_sync(0xffffffffu, v.x, d);
        v.y += __shfl_xor_sync(0xffffffffu, v.y, d);
        v.z += __shfl_xor_sync(0xffffffffu, v.z, d);
        v.w += __shfl_xor_sync(0xffffffffu, v.w, d);
    }
    if (lane < 8) {
        v.x *= 0.25f; v.y *= 0.25f; v.z *= 0.25f; v.w *= 0.25f;
        ((float4*)out)[w * 8 + lane] = v;
    }
    if (lane == 0) g_cnt[w] = 0;
}

// ---------------- launch ----------------------------------------------------
extern "C" void kernel_launch(void* const* d_in, const int* in_sizes, int n_in,
                              void* d_out, int out_size) {
    const float* h    = (const float*)d_in[0];
    const float* W    = (const float*)d_in[1];
    const float* al   = (const float*)d_in[2];
    const float* ar   = (const float*)d_in[3];
    const float* bias = (const float*)d_in[4];
    const int*   src  = (const int*)d_in[5];
    const int*   dst  = (const int*)d_in[6];
    float*       out  = (float*)d_out;

    static cudaStream_t s2 = 0;
    static cudaEvent_t evFork = 0, evJoin = 0;
    if (!s2) {
        cudaStreamCreateWithFlags(&s2, cudaStreamNonBlocking);
        cudaEventCreateWithFlags(&evFork, cudaEventDisableTiming);
        cudaEventCreateWithFlags(&evJoin, cudaEventDisableTiming);
        cudaFuncSetAttribute(k_gemm, cudaFuncAttributeMaxDynamicSharedMemorySize, SM_TOT);
    }

    // fork: prep + gemm on s2; one-pass CSR build on capture stream
    cudaEventRecord(evFork, 0);
    cudaStreamWaitEvent(s2, evFork, 0);
    k_prep<<<(128 * 64 + 255) / 256, 256, 0, s2>>>(W);
    k_gemm<<<GEMM_NB, 256, SM_TOT, s2>>>(h, al, ar);
    cudaEventRecord(evJoin, s2);

    k_build<<<(NE / 4 + 255) / 256, 256>>>(src, dst);

    cudaStreamWaitEvent(0, evJoin, 0);
    k_agg<<<(NN * 32 + 255) / 256, 256>>>(bias, out);
}

// round 17
// speedup vs baseline: 1.1601x; 1.1601x over previous
#include <cuda_runtime.h>
#include <cuda_fp16.h>
#include <cstdint>

#define NN 50000
#define NE 1600000
#define HF 128
#define NH 4
#define NF 32
#define PAD 96
#define GEMM_TILE 128
#define GEMM_NB ((NN + GEMM_TILE - 1) / GEMM_TILE)  // 391

#define TSTRIDE 136
#define TILE_HB (128 * TSTRIDE * 2)
#define SM_TOT  (2 * TILE_HB)

// ---------------- device scratch ------------------------------------------
__device__ __half2 g_feath[(size_t)NN * 64];  // projected features fp16 [N,128]
__device__ float   g_el[NN * NH];
__device__ float   g_er[NN * NH];
__device__ int     g_cnt[NN];                 // degree/cursor; starts zeroed, re-zeroed by k_agg
__device__ int     g_bin[(size_t)NN * PAD];   // padded CSR bins
__device__ __align__(16) __half g_wt[128 * TSTRIDE];  // W transposed, fp16, smem layout

__device__ __forceinline__ float lrelu(float x) {
    return x > 0.f ? x : 0.2f * x;
}

__device__ __forceinline__ uint32_t smem_u32(const void* p) {
    uint32_t a;
    asm("{ .reg .u64 t; cvta.to.shared.u64 t, %1; cvt.u32.u64 %0, t; }" : "=r"(a) : "l"(p));
    return a;
}
__device__ __forceinline__ void ldsm_x4(uint32_t addr, uint32_t* r) {
    asm volatile("ldmatrix.sync.aligned.m8n8.x4.shared.b16 {%0,%1,%2,%3}, [%4];"
                 : "=r"(r[0]), "=r"(r[1]), "=r"(r[2]), "=r"(r[3]) : "r"(addr));
}
__device__ __forceinline__ void ldsm_x2(uint32_t addr, uint32_t* r) {
    asm volatile("ldmatrix.sync.aligned.m8n8.x2.shared.b16 {%0,%1}, [%2];"
                 : "=r"(r[0]), "=r"(r[1]) : "r"(addr));
}
__device__ __forceinline__ void mma16816(float* c, const uint32_t* a, const uint32_t* b) {
    asm volatile(
        "mma.sync.aligned.m16n8k16.row.col.f32.f16.f16.f32 "
        "{%0,%1,%2,%3}, {%4,%5,%6,%7}, {%8,%9}, {%0,%1,%2,%3};"
        : "+f"(c[0]), "+f"(c[1]), "+f"(c[2]), "+f"(c[3])
        : "r"(a[0]), "r"(a[1]), "r"(a[2]), "r"(a[3]), "r"(b[0]), "r"(b[1]));
}

// ---------------- prep: W fp32 -> fp16 transposed (once, on s2) -------------
__global__ void k_prep(const float* __restrict__ W) {
    int p = blockIdx.x * blockDim.x + threadIdx.x;
    if (p >= 128 * 64) return;
    int k  = p >> 6;
    int n2 = p & 63;
    float2 v = ((const float2*)W)[p];
    g_wt[(n2 * 2)     * TSTRIDE + k] = __float2half_rn(v.x);
    g_wt[(n2 * 2 + 1) * TSTRIDE + k] = __float2half_rn(v.y);
}

// ---------------- HMMA GEMM: feat = h @ W, fused el/er ----------------------
__global__ void __launch_bounds__(256) k_gemm(const float* __restrict__ h,
                                              const float* __restrict__ attn_l,
                                              const float* __restrict__ attn_r) {
    extern __shared__ char smem[];
    __half* As = (__half*)smem;
    __half* Bs = (__half*)(smem + TILE_HB);
    uint32_t sA = smem_u32(As);
    uint32_t sB = smem_u32(Bs);

    int tid  = threadIdx.x;
    int wid  = tid >> 5;
    int lane = tid & 31;
    int base = blockIdx.x * GEMM_TILE;

    for (int p = tid; p < 128 * 64; p += 256) {
        int r  = p >> 6;
        int c2 = p & 63;
        float2 v = make_float2(0.f, 0.f);
        int gr = base + r;
        if (gr < NN) v = *(const float2*)&h[(size_t)gr * 128 + c2 * 2];
        *(__half2*)&As[r * TSTRIDE + c2 * 2] = __floats2half2_rn(v.x, v.y);
    }
    for (int p = tid; p < TILE_HB / 16; p += 256)
        ((uint4*)Bs)[p] = ((const uint4*)g_wt)[p];
    __syncthreads();

    int mrow0 = (wid >> 1) * 32;
    int ncol0 = (wid & 1) * 64;

    float acc[2][8][4];
#pragma unroll
    for (int mi = 0; mi < 2; mi++)
#pragma unroll
        for (int ni = 0; ni < 8; ni++)
#pragma unroll
            for (int j = 0; j < 4; j++) acc[mi][ni][j] = 0.f;

#pragma unroll
    for (int ks = 0; ks < 8; ks++) {
        int k0 = ks * 16;
        uint32_t a[2][4];
#pragma unroll
        for (int mi = 0; mi < 2; mi++) {
            int row = mrow0 + mi * 16 + (lane & 15);
            int col = k0 + (lane >> 4) * 8;
            ldsm_x4(sA + (row * TSTRIDE + col) * 2, a[mi]);
        }
        uint32_t b[8][2];
#pragma unroll
        for (int ni = 0; ni < 8; ni++) {
            int n = ncol0 + ni * 8 + (lane & 7);
            int k = k0 + ((lane >> 3) & 1) * 8;
            ldsm_x2(sB + (n * TSTRIDE + k) * 2, b[ni]);
        }
#pragma unroll
        for (int mi = 0; mi < 2; mi++)
#pragma unroll
            for (int ni = 0; ni < 8; ni++)
                mma16816(acc[mi][ni], a[mi], b[ni]);
    }
    __syncthreads();

    __half* Cs = As;
#pragma unroll
    for (int mi = 0; mi < 2; mi++) {
        int r0 = mrow0 + mi * 16 + (lane >> 2);
#pragma unroll
        for (int ni = 0; ni < 8; ni++) {
            int cb = ncol0 + ni * 8 + (lane & 3) * 2;
            *(__half2*)&Cs[r0 * TSTRIDE + cb]       = __floats2half2_rn(acc[mi][ni][0], acc[mi][ni][1]);
            *(__half2*)&Cs[(r0 + 8) * TSTRIDE + cb] = __floats2half2_rn(acc[mi][ni][2], acc[mi][ni][3]);
        }
    }
    __syncthreads();

    float4 al = ((const float4*)attn_l)[lane];
    float4 ar = ((const float4*)attn_r)[lane];
    int hh = lane >> 3;

    for (int i = 0; i < 16; i++) {
        int r  = wid * 16 + i;
        int gr = base + r;
        uint2 u = *(uint2*)&Cs[r * TSTRIDE + lane * 4];
        float2 f0 = __half22float2(*(__half2*)&u.x);
        float2 f1 = __half22float2(*(__half2*)&u.y);
        if (gr < NN) ((uint2*)g_feath)[(size_t)gr * 32 + lane] = u;

        float pl = f0.x * al.x + f0.y * al.y + f1.x * al.z + f1.y * al.w;
        float pr = f0.x * ar.x + f0.y * ar.y + f1.x * ar.z + f1.y * ar.w;
#pragma unroll
        for (int d = 4; d >= 1; d >>= 1) {
            pl += __shfl_down_sync(0xffffffffu, pl, d, 8);
            pr += __shfl_down_sync(0xffffffffu, pr, d, 8);
        }
        if (gr < NN && (lane & 7) == 0) {
            g_el[gr * 4 + hh] = pl;
            g_er[gr * 4 + hh] = pr;
        }
    }
}

// ---------------- one-pass padded-bin CSR build (4 edges/thread) ------------
__global__ void k_build(const int* __restrict__ src, const int* __restrict__ dst) {
    int q = blockIdx.x * blockDim.x + threadIdx.x;
    if (q >= NE / 4) return;
    int4 s4 = ((const int4*)src)[q];
    int4 d4 = ((const int4*)dst)[q];
    int p0 = atomicAdd(&g_cnt[d4.x], 1);
    int p1 = atomicAdd(&g_cnt[d4.y], 1);
    int p2 = atomicAdd(&g_cnt[d4.z], 1);
    int p3 = atomicAdd(&g_cnt[d4.w], 1);
    if (p0 < PAD) g_bin[(size_t)d4.x * PAD + p0] = s4.x;
    if (p1 < PAD) g_bin[(size_t)d4.y * PAD + p1] = s4.y;
    if (p2 < PAD) g_bin[(size_t)d4.z * PAD + p2] = s4.z;
    if (p3 < PAD) g_bin[(size_t)d4.w * PAD + p3] = s4.w;
}

// ---------------- fused aggregate: softmax + fp16 gather + epilogue ---------
// round-15 layout; full 32-edge stages take a branchless fully-unrolled path.
__global__ void __launch_bounds__(256) k_agg(const float* __restrict__ bias,
                                             float* __restrict__ out) {
    __shared__ int   s_s[8][32];
    __shared__ float s_ex[8][4][32];

    int w    = (blockIdx.x * blockDim.x + threadIdx.x) >> 5;
    int lane = threadIdx.x & 31;
    int wl   = threadIdx.x >> 5;
    if (w >= NN) return;

    int deg = g_cnt[w];
    if (deg > PAD) deg = PAD;
    int start = w * PAD;
    int end   = start + deg;
    float4 erd = ((const float4*)g_er)[w];
    int hh = lane >> 3;

    float4 acc  = make_float4(0.f, 0.f, 0.f, 0.f);
    float4 dsum = make_float4(0.f, 0.f, 0.f, 0.f);

    int    ps = 0;
    float4 pa = make_float4(0.f, 0.f, 0.f, 0.f);
    bool   pv = (start + lane) < end;
    if (pv) {
        ps = __ldg(&g_bin[(size_t)start + lane]);
        pa = ((const float4*)g_el)[ps];
    }

    const uint2* fbase = &((const uint2*)g_feath)[lane];

    for (int base = start; base < end; base += 32) {
        float4 ex4 = make_float4(0.f, 0.f, 0.f, 0.f);
        if (pv) {
            ex4.x = __expf(lrelu(pa.x + erd.x));
            ex4.y = __expf(lrelu(pa.y + erd.y));
            ex4.z = __expf(lrelu(pa.z + erd.z));
            ex4.w = __expf(lrelu(pa.w + erd.w));
            dsum.x += ex4.x; dsum.y += ex4.y; dsum.z += ex4.z; dsum.w += ex4.w;
        }
        s_s[wl][lane]     = ps;
        s_ex[wl][0][lane] = ex4.x;
        s_ex[wl][1][lane] = ex4.y;
        s_ex[wl][2][lane] = ex4.z;
        s_ex[wl][3][lane] = ex4.w;
        __syncwarp();

        // next-stage prefetch overlaps the j-loop
        int ne = base + 32 + lane;
        pv = ne < end;
        ps = 0;
        if (pv) {
            ps = __ldg(&g_bin[(size_t)ne]);
            pa = ((const float4*)g_el)[ps];
        }

        int cnt = end - base;
        if (cnt >= 32) {
            // branchless fast path: fixed 32 iterations, no per-iter bounds test
#pragma unroll
            for (int j = 0; j < 32; j++) {
                int   sj = s_s[wl][j];
                float aj = s_ex[wl][hh][j];
                uint2 u  = __ldg(fbase + (size_t)sj * 32);
                float2 f0 = __half22float2(*(__half2*)&u.x);
                float2 f1 = __half22float2(*(__half2*)&u.y);
                acc.x += f0.x * aj;
                acc.y += f0.y * aj;
                acc.z += f1.x * aj;
                acc.w += f1.y * aj;
            }
        } else {
#pragma unroll 8
            for (int j = 0; j < cnt; j++) {
                int   sj = s_s[wl][j];
                float aj = s_ex[wl][hh][j];
                uint2 u  = __ldg(fbase + (size_t)sj * 32);
                float2 f0 = __half22float2(*(__half2*)&u.x);
                float2 f1 = __half22float2(*(__half2*)&u.y);
                acc.x += f0.x * aj;
                acc.y += f0.y * aj;
                acc.z += f1.x * aj;
                acc.w += f1.y * aj;
            }
        }
        __syncwarp();
    }

#pragma unroll
    for (int d = 16; d >= 1; d >>= 1) {
        dsum.x += __shfl_xor_sync(0xffffffffu, dsum.x, d);
        dsum.y += __shfl_xor_sync(0xffffffffu, dsum.y, d);
        dsum.z += __shfl_xor_sync(0xffffffffu, dsum.z, d);
        dsum.w += __shfl_xor_sync(0xffffffffu, dsum.w, d);
    }
    float dh = (hh == 0) ? dsum.x : (hh == 1) ? dsum.y : (hh == 2) ? dsum.z : dsum.w;
    float r  = 1.f / fmaxf(dh, 1e-9f);

    float4 b4 = ((const float4*)bias)[lane];
    float4 v;
    v.x = fmaxf(acc.x * r + b4.x, 0.f);
    v.y = fmaxf(acc.y * r + b4.y, 0.f);
    v.z = fmaxf(acc.z * r + b4.z, 0.f);
    v.w = fmaxf(acc.w * r + b4.w, 0.f);

#pragma unroll
    for (int d = 8; d <= 16; d <<= 1) {
        v.x += __shfl_xor_sync(0xffffffffu, v.x, d);
        v.y += __shfl_xor_sync(0xffffffffu, v.y, d);
        v.z += __shfl_xor_sync(0xffffffffu, v.z, d);
        v.w += __shfl_xor_sync(0xffffffffu, v.w, d);
    }
    if (lane < 8) {
        v.x *= 0.25f; v.y *= 0.25f; v.z *= 0.25f; v.w *= 0.25f;
        ((float4*)out)[w * 8 + lane] = v;
    }
    if (lane == 0) g_cnt[w] = 0;
}

// ---------------- launch ----------------------------------------------------
extern "C" void kernel_launch(void* const* d_in, const int* in_sizes, int n_in,
                              void* d_out, int out_size) {
    const float* h    = (const float*)d_in[0];
    const float* W    = (const float*)d_in[1];
    const float* al   = (const float*)d_in[2];
    const float* ar   = (const float*)d_in[3];
    const float* bias = (const float*)d_in[4];
    const int*   src  = (const int*)d_in[5];
    const int*   dst  = (const int*)d_in[6];
    float*       out  = (float*)d_out;

    static cudaStream_t s2 = 0;
    static cudaEvent_t evFork = 0, evJoin = 0;
    if (!s2) {
        cudaStreamCreateWithFlags(&s2, cudaStreamNonBlocking);
        cudaEventCreateWithFlags(&evFork, cudaEventDisableTiming);
        cudaEventCreateWithFlags(&evJoin, cudaEventDisableTiming);
        cudaFuncSetAttribute(k_gemm, cudaFuncAttributeMaxDynamicSharedMemorySize, SM_TOT);
    }

    // fork: prep + gemm on s2; one-pass CSR build on capture stream
    cudaEventRecord(evFork, 0);
    cudaStreamWaitEvent(s2, evFork, 0);
    k_prep<<<(128 * 64 + 255) / 256, 256, 0, s2>>>(W);
    k_gemm<<<GEMM_NB, 256, SM_TOT, s2>>>(h, al, ar);
    cudaEventRecord(evJoin, s2);

    k_build<<<(NE / 4 + 255) / 256, 256>>>(src, dst);

    cudaStreamWaitEvent(0, evJoin, 0);
    k_agg<<<(NN * 32 + 255) / 256, 256>>>(bias, out);
}